// round 15
// baseline (speedup 1.0000x reference)
#include <cuda_runtime.h>
#include <math.h>

#define BATCH 4096
#define DIN   64
#define HID   256
#define NB    30
#define NDOF  7
#define OUTC  217
#define NS    51
#define DTC   0.002f
#define AZBZ  56.25f
// ln(float(0.998)) and ln(0.985)
#define LNX   (-0.0020019769f)
#define LNLAM (-0.015113638f)
#define WCW   400                 // padded width of Wc
#define OUTW  (NS * NDOF)         // 357

__device__ float g_feat[BATCH * HID];
// Wc: [k][col]; col = d*56 + s (s<51; 51..55 stay 0), col = 392+d -> goal col d.
// zero-init (static), pad cols never written.
__device__ __align__(16) float g_wc[HID * WCW];
__device__ float g_abg[3 * 56];   // alpha/beta/gamma per sample (padded)
__device__ float g_bc[7 * 56];    // bias contraction  sum_n delta[s,n]*bl[7+30d+n]
__device__ float g_blg[8];        // bl[0..6]

typedef unsigned long long ull;
__device__ __forceinline__ void fma2(ull& d, ull a, ull b) {
    asm("fma.rn.f32x2 %0, %1, %2, %0;" : "+l"(d) : "l"(a), "l"(b));
}
__device__ __forceinline__ float lo32(ull v) { return __uint_as_float((unsigned)v); }
__device__ __forceinline__ float hi32(ull v) { return __uint_as_float((unsigned)(v >> 32)); }

__device__ __forceinline__ float tanh_fast(float x) {
    float e = __expf(2.f * x);
    return 1.f - __fdividef(2.f, e + 1.f);
}

__device__ __forceinline__ void pdl_wait() {
    asm volatile("griddepcontrol.wait;" ::: "memory");
}
__device__ __forceinline__ void pdl_trigger() {
    asm volatile("griddepcontrol.launch_dependents;" ::: "memory");
}

// ---------------------------------------------------------------------------
// K1: Wc builders (blocks 0..48) + misc (49) + gemm1 64x64 tiles (50..305).
// Wc block (d, s-group of 8): self-contained forcing table + conv -> delta,
// then Wc[k][d*56+s] = sum_n delta[s,n] * WL[k][7+30d+n].
// ---------------------------------------------------------------------------
#define K1_SMEM 65536

__global__ __launch_bounds__(256) void k1_kernel(const float* __restrict__ X,
                                                 const float* __restrict__ Wp,
                                                 const float* __restrict__ bp,
                                                 const float* __restrict__ Wl,
                                                 const float* __restrict__ bl,
                                                 const float* __restrict__ c,
                                                 const float* __restrict__ h) {
    extern __shared__ __align__(16) float sm[];
    const int tid = threadIdx.x;
    const int bid = blockIdx.x;

    if (bid < 49) {
        // ---- Wc builder for dof d, samples s0..s0+7 ----
        const int d  = bid / 7;
        const int sg = bid % 7;
        const int s0 = sg * 8;
        const int smax = (s0 + 7 < 50) ? (s0 + 7) : 50;
        const int Tmax = smax * 10;

        float* sc    = sm;              // [32]
        float* sh    = sm + 32;         // [32]
        float* skw   = sm + 64;         // [504]
        float* gtab  = sm + 568;        // [30][504]
        float* delta = sm + 568 + 15120; // [8][32]

        if (tid < NB) { sc[tid] = c[tid]; sh[tid] = h[tid]; }
        __syncthreads();

        // forcing table + kw table, i = 1..Tmax-1
        for (int i = tid + 1; i < Tmax; i += 256) {
            skw[i] = (float)i * __expf(LNLAM * (float)(i - 1));
            float x = __expf(LNX * (float)i);
            float psi[NB];
            float S = 0.f;
#pragma unroll
            for (int n = 0; n < NB; n++) {
                float dd = x - sc[n];
                float p = __expf(-sh[n] * dd * dd);
                psi[n] = p; S += p;
            }
            float sc2 = x / S;
#pragma unroll
            for (int n = 0; n < NB; n++) gtab[n * 504 + i] = psi[n] * sc2;
        }
        __syncthreads();

        // conv: thread = (sl, ch)
        {
            int sl = tid >> 5, ch = tid & 31;
            int s = s0 + sl;
            if (ch < NB && s <= 50) {
                int T = s * 10;
                float acc = 0.f;
                const float* gr = gtab + ch * 504;
                for (int k = 1; k < T; k++) acc += skw[k] * gr[T - k];
                delta[sl * 32 + ch] = (DTC * DTC) * acc;
            }
        }
        __syncthreads();

        // bias contraction bc[d][s]
        if (tid < 8) {
            int s = s0 + tid;
            if (s <= 50) {
                float acc = 0.f;
#pragma unroll
                for (int n = 0; n < NB; n++) acc += delta[tid * 32 + n] * bl[7 + 30 * d + n];
                g_bc[d * 56 + s] = acc;
            }
        }
        // Wc columns: thread = k
        {
            int k = tid;
            float w[NB];
            const float* wr = Wl + k * OUTC + 7 + 30 * d;
#pragma unroll
            for (int n = 0; n < NB; n++) w[n] = wr[n];
#pragma unroll
            for (int sl = 0; sl < 8; sl++) {
                int s = s0 + sl;
                if (s <= 50) {
                    float acc = 0.f;
#pragma unroll
                    for (int n = 0; n < NB; n++) acc += w[n] * delta[sl * 32 + n];
                    g_wc[k * WCW + d * 56 + s] = acc;
                }
            }
        }
    } else if (bid == 49) {
        // ---- misc: alpha/beta/gamma closed form, goal cols, bl ----
        if (tid < NS) {
            float T = (float)(tid * 10);
            float lamT1 = __expf(LNLAM * (T - 1.f));
            float lamT  = __expf(LNLAM * T);
            float kwT = T * lamT1;
            g_abg[0 * 56 + tid] = 0.05f * DTC * kwT;
            g_abg[1 * 56 + tid] = lamT + 0.015f * kwT;
            // sum_{k=1}^{T-1} k lam^{k-1} = (1 - T lam^{T-1} + (T-1) lam^T)/(1-lam)^2
            float Ssum = (1.f - lamT) * (1.f / 0.000225f) - T * lamT1 * (1.f / 0.015f);
            g_abg[2 * 56 + tid] = AZBZ * (DTC * DTC) * Ssum;
        }
        if (tid >= 64 && tid < 71) g_blg[tid - 64] = bl[tid - 64];
        // goal cols: Wc[k][392+d] = WL[k][d]
        for (int i = tid; i < 256 * 7; i += 256) {
            int k = i / 7, dd = i - (i / 7) * 7;
            g_wc[k * WCW + 392 + dd] = Wl[k * OUTC + dd];
        }
    } else {
        // ---- gemm1 64x64 tile: feat = tanh(x @ W_pt + b_pt) ----
        float  (*As)[68] = reinterpret_cast<float(*)[68]>(sm);          // [k][m]
        float2 (*Bs)[66] = reinterpret_cast<float2(*)[66]>(sm + 4352);  // [k][n] dup
        const int t = bid - 50;
        const int bm = (t & 63) * 64;
        const int bn = (t >> 6) * 64;

#pragma unroll
        for (int it = 0; it < 4; it++) {
            int id = tid + it * 256;
            int m = id >> 4, k4 = (id & 15) << 2;
            float4 v = *reinterpret_cast<const float4*>(X + (bm + m) * DIN + k4);
            As[k4 + 0][m] = v.x; As[k4 + 1][m] = v.y;
            As[k4 + 2][m] = v.z; As[k4 + 3][m] = v.w;
        }
#pragma unroll
        for (int it = 0; it < 4; it++) {
            int id = tid + it * 256;
            int k = id >> 4, n4 = (id & 15) << 2;
            float4 v = *reinterpret_cast<const float4*>(Wp + k * HID + bn + n4);
            Bs[k][n4 + 0] = make_float2(v.x, v.x);
            Bs[k][n4 + 1] = make_float2(v.y, v.y);
            Bs[k][n4 + 2] = make_float2(v.z, v.z);
            Bs[k][n4 + 3] = make_float2(v.w, v.w);
        }
        __syncthreads();

        const int ty = tid >> 4, tx = tid & 15;
        ull acc[2][4];
#pragma unroll
        for (int i = 0; i < 2; i++)
#pragma unroll
            for (int j = 0; j < 4; j++) acc[i][j] = 0ull;

#pragma unroll
        for (int k = 0; k < 64; k++) {
            float4 a = *reinterpret_cast<const float4*>(&As[k][ty * 4]);
            ull p0 = *reinterpret_cast<const ull*>(&a.x);
            ull p1 = *reinterpret_cast<const ull*>(&a.z);
#pragma unroll
            for (int j = 0; j < 4; j++) {
                ull b = *reinterpret_cast<const ull*>(&Bs[k][tx + 16 * j]);
                fma2(acc[0][j], p0, b);
                fma2(acc[1][j], p1, b);
            }
        }

#pragma unroll
        for (int j = 0; j < 4; j++) {
            int col = bn + tx + 16 * j;
            float bb = bp[col];
            int r = bm + ty * 4;
            g_feat[(r + 0) * HID + col] = tanh_fast(lo32(acc[0][j]) + bb);
            g_feat[(r + 1) * HID + col] = tanh_fast(hi32(acc[0][j]) + bb);
            g_feat[(r + 2) * HID + col] = tanh_fast(lo32(acc[1][j]) + bb);
            g_feat[(r + 3) * HID + col] = tanh_fast(hi32(acc[1][j]) + bb);
        }
    }
    pdl_trigger();
}

// ---------------------------------------------------------------------------
// K2: fused p-GEMM + DMP epilogue. Block = [64 rows x dof d], grid (64, 7).
// p[b][s] = feat[b,:] @ Wc[:, d*56+s]; goal = feat @ Wc[:, 392+d].
// y = alpha + beta*y0 + gamma*goal + (goal - y0)*(p + bc).
// ---------------------------------------------------------------------------
__global__ __launch_bounds__(256) void k2_kernel(const float* __restrict__ state,
                                                 float* __restrict__ out) {
    __shared__ __align__(16) float  As[32][66];   // [k][m]
    __shared__ __align__(16) float2 Bs[32][58];   // [k][col] duplicated; col 56 = goal
    __shared__ float sal[56], sbe[56], sga[56], sbc[56];
    __shared__ float sblg;

    const int tid = threadIdx.x;
    const int bm = blockIdx.x * 64;
    const int d  = blockIdx.y;
    const int ty = tid >> 3;      // 0..31 (row pair)
    const int tx = tid & 7;       // 0..7

    pdl_wait();   // g_feat, g_wc, g_abg, g_bc, g_blg valid

    if (tid < 56) {
        sal[tid] = g_abg[tid];
        sbe[tid] = g_abg[56 + tid];
        sga[tid] = g_abg[112 + tid];
        sbc[tid] = g_bc[d * 56 + tid];
    }
    if (tid == 56) sblg = g_blg[d];

    ull accp[7];
    ull accg = 0ull;
#pragma unroll
    for (int j = 0; j < 7; j++) accp[j] = 0ull;

    for (int k0 = 0; k0 < HID; k0 += 32) {
        __syncthreads();
        // A fill: 64 rows x 32 k, transposed
#pragma unroll
        for (int it = 0; it < 2; it++) {
            int id = tid + it * 256;          // 0..511
            int m = id >> 3, k4 = (id & 7) << 2;
            float4 v = *reinterpret_cast<const float4*>(g_feat + (bm + m) * HID + k0 + k4);
            As[k4 + 0][m] = v.x; As[k4 + 1][m] = v.y;
            As[k4 + 2][m] = v.z; As[k4 + 3][m] = v.w;
        }
        // B fill: 32 x 57 (56 p-cols + goal col), duplicated
#pragma unroll
        for (int it = 0; it < 8; it++) {
            int id = tid + it * 256;
            if (id < 32 * 57) {
                int kk = id / 57, cc = id - kk * 57;
                int col = (cc < 56) ? (d * 56 + cc) : (392 + d);
                float v = g_wc[(k0 + kk) * WCW + col];
                Bs[kk][cc] = make_float2(v, v);
            }
        }
        __syncthreads();

#pragma unroll
        for (int kk = 0; kk < 32; kk++) {
            ull a = *reinterpret_cast<const ull*>(&As[kk][ty * 2]);
#pragma unroll
            for (int j = 0; j < 7; j++) {
                ull b = *reinterpret_cast<const ull*>(&Bs[kk][tx + 8 * j]);
                fma2(accp[j], a, b);
            }
            ull bg = *reinterpret_cast<const ull*>(&Bs[kk][56]);
            fma2(accg, a, bg);
        }
    }

    // epilogue
    const int r0 = bm + ty * 2;
    float blgd = sblg;
    float y00 = state[r0 * NDOF + d];
    float y01 = state[(r0 + 1) * NDOF + d];
    float g0 = lo32(accg) + blgd;
    float g1 = hi32(accg) + blgd;
    float gy0 = g0 - y00, gy1 = g1 - y01;
#pragma unroll
    for (int j = 0; j < 7; j++) {
        int s = tx + 8 * j;
        if (s < NS) {
            float al = sal[s], be = sbe[s], ga = sga[s], bcs = sbc[s];
            float p0 = lo32(accp[j]) + bcs;
            float p1 = hi32(accp[j]) + bcs;
            out[(size_t)r0 * OUTW + s * NDOF + d]       = al + be * y00 + ga * g0 + gy0 * p0;
            out[(size_t)(r0 + 1) * OUTW + s * NDOF + d] = al + be * y01 + ga * g1 + gy1 * p1;
        }
    }
    pdl_trigger();
}

// ---------------------------------------------------------------------------
extern "C" void kernel_launch(void* const* d_in, const int* in_sizes, int n_in,
                              void* d_out, int out_size) {
    const float* x      = (const float*)d_in[0];
    const float* state  = (const float*)d_in[1];
    const float* W_pt   = (const float*)d_in[2];
    const float* b_pt   = (const float*)d_in[3];
    const float* W_last = (const float*)d_in[4];
    const float* b_last = (const float*)d_in[5];
    const float* c      = (const float*)d_in[6];
    const float* h      = (const float*)d_in[7];
    float* out = (float*)d_out;

    static int init_done = 0;
    if (!init_done) {
        cudaFuncSetAttribute(k1_kernel, cudaFuncAttributeMaxDynamicSharedMemorySize,
                             K1_SMEM);
        init_done = 1;
    }

    // K1: Wc builders (0..48) + misc (49) + gemm1 (50..305)
    k1_kernel<<<306, 256, K1_SMEM>>>(x, W_pt, b_pt, W_last, b_last, c, h);

    // K2: fused p-GEMM + epilogue -> final output, PDL-chained to K1
    {
        cudaLaunchConfig_t cfg = {};
        cfg.gridDim = dim3(BATCH / 64, NDOF, 1);
        cfg.blockDim = dim3(256, 1, 1);
        cfg.dynamicSmemBytes = 0;
        cfg.stream = 0;
        cudaLaunchAttribute attr[1];
        attr[0].id = cudaLaunchAttributeProgrammaticStreamSerialization;
        attr[0].val.programmaticStreamSerializationAllowed = 1;
        cfg.attrs = attr;
        cfg.numAttrs = 1;
        cudaLaunchKernelEx(&cfg, k2_kernel, (const float*)state, (float*)out);
    }
}

// round 16
// speedup vs baseline: 2.0820x; 2.0820x over previous
#include <cuda_runtime.h>
#include <math.h>

#define BATCH 4096
#define DIN   64
#define HID   256
#define NB    30
#define NDOF  7
#define OUTC  217
#define NS    51
#define DTC   0.002f
#define AZBZ  56.25f
// ln(float(0.998)) and ln(0.985)
#define LNX   (-0.0020019769f)
#define LNLAM (-0.015113638f)
#define GW    501
#define BO    (BATCH * OUTC)

__device__ float g_feat[BATCH * HID];
__device__ float g_out217[2 * BO];       // two split-K partials
// coefficients, transposed [ch][slot], slot=(s/7)*8+s%7, duplicated as float2;
// padding slots never written -> stay 0 (static zero-init).
__device__ __align__(16) float2 g_coef_t[33 * 64];

typedef unsigned long long ull;
__device__ __forceinline__ void fma2(ull& d, ull a, ull b) {
    asm("fma.rn.f32x2 %0, %1, %2, %0;" : "+l"(d) : "l"(a), "l"(b));
}
__device__ __forceinline__ float lo32(ull v) { return __uint_as_float((unsigned)v); }
__device__ __forceinline__ float hi32(ull v) { return __uint_as_float((unsigned)(v >> 32)); }

// fast tanh: 1 - 2/(e^{2x}+1). MUFU-based, rel err ~1e-6; correct limits.
__device__ __forceinline__ float tanh_fast(float x) {
    float e = __expf(2.f * x);
    return 1.f - __fdividef(2.f, e + 1.f);
}

// --- PDL primitives -------------------------------------------------------
__device__ __forceinline__ void pdl_wait() {
    asm volatile("griddepcontrol.wait;" ::: "memory");
}
__device__ __forceinline__ void pdl_trigger() {
    asm volatile("griddepcontrol.launch_dependents;" ::: "memory");
}

// ---------------------------------------------------------------------------
// K1: coef blocks (0..50) + gemm1 tiles (51..306). smem = gemm1's 51200 B.
// coef: thread-per-k convolution, register accumulators, shuffle reduction.
// ---------------------------------------------------------------------------
#define K1_SMEM 51200

__global__ __launch_bounds__(256) void k1_kernel(const float* __restrict__ X,
                                                 const float* __restrict__ Wp,
                                                 const float* __restrict__ bp,
                                                 const float* __restrict__ c,
                                                 const float* __restrict__ h) {
    extern __shared__ __align__(16) float sm[];
    const int tid = threadIdx.x;
    const int bid = blockIdx.x;

    if (bid < 51) {
        // ---- coef block for sample s = bid ----
        float* sc  = sm;          // [32]
        float* sh  = sm + 32;     // [32]
        float* red = sm + 64;     // [8][31]

        if (tid < NB) { sc[tid] = c[tid]; sh[tid] = h[tid]; }
        __syncthreads();

        const int s = bid;
        const int T = s * 10;
        const int slot = (s / 7) * 8 + (s % 7);

        float acc[31];
#pragma unroll
        for (int n = 0; n < 31; n++) acc[n] = 0.f;

        for (int k = tid + 1; k < T; k += 256) {
            float kw = (float)k * __expf(LNLAM * (float)(k - 1));
            float x  = __expf(LNX * (float)(T - k));
            float S = 0.f;
#pragma unroll
            for (int n = 0; n < NB; n++) {
                float d = x - sc[n];
                S += __expf(-sh[n] * d * d);
            }
            float sc2 = kw * x / S;
#pragma unroll
            for (int n = 0; n < NB; n++) {
                float d = x - sc[n];
                acc[n] += __expf(-sh[n] * d * d) * sc2;
            }
            acc[30] += kw;
        }

#pragma unroll
        for (int off = 16; off > 0; off >>= 1)
#pragma unroll
            for (int n = 0; n < 31; n++)
                acc[n] += __shfl_down_sync(0xffffffffu, acc[n], off);

        const int wid = tid >> 5, lane = tid & 31;
        if (lane == 0)
#pragma unroll
            for (int n = 0; n < 31; n++) red[wid * 31 + n] = acc[n];
        __syncthreads();

        if (tid < 31) {
            float sum = 0.f;
#pragma unroll
            for (int w = 0; w < 8; w++) sum += red[w * 31 + tid];
            if (tid < NB) {
                float v = (DTC * DTC) * sum;
                g_coef_t[(3 + tid) * 64 + slot] = make_float2(v, v);
            } else {
                float v = AZBZ * (DTC * DTC) * sum;
                g_coef_t[2 * 64 + slot] = make_float2(v, v);
            }
        }
        if (tid == 32) {
            float kwT = (float)T * __expf(LNLAM * (float)(T - 1));
            float v = 0.05f * DTC * kwT;
            g_coef_t[0 * 64 + slot] = make_float2(v, v);
        }
        if (tid == 33) {
            float kwT = (float)T * __expf(LNLAM * (float)(T - 1));
            float v = __expf(LNLAM * (float)T) + 0.015f * kwT;
            g_coef_t[1 * 64 + slot] = make_float2(v, v);
        }
    } else {
        // ---- gemm1 tile: feat = tanh(x @ W_pt + b_pt) ----
        float  (*As)[68] = reinterpret_cast<float(*)[68]>(sm);          // [k][m]
        float2 (*Bs)[66] = reinterpret_cast<float2(*)[66]>(sm + 4352);  // [k][n] dup
        const int t = bid - 51;
        const int bm = (t & 63) * 64;
        const int bn = (t >> 6) * 64;

#pragma unroll
        for (int it = 0; it < 4; it++) {
            int id = tid + it * 256;
            int m = id >> 4, k4 = (id & 15) << 2;
            float4 v = *reinterpret_cast<const float4*>(X + (bm + m) * DIN + k4);
            As[k4 + 0][m] = v.x; As[k4 + 1][m] = v.y;
            As[k4 + 2][m] = v.z; As[k4 + 3][m] = v.w;
        }
#pragma unroll
        for (int it = 0; it < 4; it++) {
            int id = tid + it * 256;
            int k = id >> 4, n4 = (id & 15) << 2;
            float4 v = *reinterpret_cast<const float4*>(Wp + k * HID + bn + n4);
            Bs[k][n4 + 0] = make_float2(v.x, v.x);
            Bs[k][n4 + 1] = make_float2(v.y, v.y);
            Bs[k][n4 + 2] = make_float2(v.z, v.z);
            Bs[k][n4 + 3] = make_float2(v.w, v.w);
        }
        __syncthreads();

        const int ty = tid >> 4, tx = tid & 15;
        ull acc[2][4];
#pragma unroll
        for (int i = 0; i < 2; i++)
#pragma unroll
            for (int j = 0; j < 4; j++) acc[i][j] = 0ull;

#pragma unroll
        for (int k = 0; k < 64; k++) {
            float4 a = *reinterpret_cast<const float4*>(&As[k][ty * 4]);
            ull p0 = *reinterpret_cast<const ull*>(&a.x);
            ull p1 = *reinterpret_cast<const ull*>(&a.z);
#pragma unroll
            for (int j = 0; j < 4; j++) {
                ull b = *reinterpret_cast<const ull*>(&Bs[k][tx + 16 * j]);
                fma2(acc[0][j], p0, b);
                fma2(acc[1][j], p1, b);
            }
        }

#pragma unroll
        for (int j = 0; j < 4; j++) {
            int col = bn + tx + 16 * j;
            float bb = bp[col];
            int r = bm + ty * 4;
            g_feat[(r + 0) * HID + col] = tanh_fast(lo32(acc[0][j]) + bb);
            g_feat[(r + 1) * HID + col] = tanh_fast(hi32(acc[0][j]) + bb);
            g_feat[(r + 2) * HID + col] = tanh_fast(lo32(acc[1][j]) + bb);
            g_feat[(r + 3) * HID + col] = tanh_fast(hi32(acc[1][j]) + bb);
        }
    }
    pdl_trigger();
}

// ---------------------------------------------------------------------------
// K2: GEMM2 (split-K x2): partial[z] = feat[:, z*128:(z+1)*128] @ Wl[z half].
// B-fragment prefetch before pdl_wait overlaps K1's tail.
// ---------------------------------------------------------------------------
__global__ __launch_bounds__(256) void gemm2_kernel(const float* __restrict__ Wl,
                                                    const float* __restrict__ bl) {
    __shared__ __align__(16) float  As[32][68];   // [k][m]
    __shared__ float2 Bs[32][114];                // [k][n] duplicated
    const int tid = threadIdx.x;
    const int bm = blockIdx.x * 64;
    const int bn = blockIdx.y * 112;
    const int z  = blockIdx.z;
    const int kbase = z * 128;
    const int ty = tid >> 4, tx = tid & 15;

    const int am = tid >> 3;
    const int ak4 = (tid & 7) << 2;

    float4 ra[2];
    float rb[14];

    // B prefetch (input only) — before the PDL wait
#pragma unroll
    for (int it = 0; it < 14; it++) {
        int id = tid + it * 256;
        int kk = id / 112, cc = id - kk * 112;
        rb[it] = (bn + cc < OUTC) ? Wl[(kbase + kk) * OUTC + bn + cc] : 0.f;
    }

    pdl_wait();   // feat (K1 output) valid from here

#pragma unroll
    for (int it = 0; it < 2; it++)
        ra[it] = *reinterpret_cast<const float4*>(
            g_feat + (bm + am + it * 32) * HID + kbase + ak4);

    ull acc[2][7];
#pragma unroll
    for (int i = 0; i < 2; i++)
#pragma unroll
        for (int j = 0; j < 7; j++) acc[i][j] = 0ull;

    for (int k0 = 0; k0 < 128; k0 += 32) {
#pragma unroll
        for (int it = 0; it < 2; it++) {
            int m = am + it * 32;
            As[ak4 + 0][m] = ra[it].x; As[ak4 + 1][m] = ra[it].y;
            As[ak4 + 2][m] = ra[it].z; As[ak4 + 3][m] = ra[it].w;
        }
#pragma unroll
        for (int it = 0; it < 14; it++) {
            int id = tid + it * 256;
            int kk = id / 112, cc = id - kk * 112;
            Bs[kk][cc] = make_float2(rb[it], rb[it]);
        }
        __syncthreads();

        if (k0 + 32 < 128) {
#pragma unroll
            for (int it = 0; it < 2; it++)
                ra[it] = *reinterpret_cast<const float4*>(
                    g_feat + (bm + am + it * 32) * HID + kbase + k0 + 32 + ak4);
#pragma unroll
            for (int it = 0; it < 14; it++) {
                int id = tid + it * 256;
                int kk = id / 112, cc = id - kk * 112;
                rb[it] = (bn + cc < OUTC)
                           ? Wl[(kbase + k0 + 32 + kk) * OUTC + bn + cc] : 0.f;
            }
        }

#pragma unroll
        for (int kk = 0; kk < 32; kk++) {
            float4 a = *reinterpret_cast<const float4*>(&As[kk][ty * 4]);
            ull p0 = *reinterpret_cast<const ull*>(&a.x);
            ull p1 = *reinterpret_cast<const ull*>(&a.z);
#pragma unroll
            for (int j = 0; j < 7; j++) {
                ull b = *reinterpret_cast<const ull*>(&Bs[kk][tx + 16 * j]);
                fma2(acc[0][j], p0, b);
                fma2(acc[1][j], p1, b);
            }
        }
        __syncthreads();
    }

    float* outp = g_out217 + z * BO;
#pragma unroll
    for (int j = 0; j < 7; j++) {
        int col = bn + tx + 16 * j;
        if (col < OUTC) {
            float bb = (z == 0) ? bl[col] : 0.f;
            int r = bm + ty * 4;
            outp[(r + 0) * OUTC + col] = lo32(acc[0][j]) + bb;
            outp[(r + 1) * OUTC + col] = hi32(acc[0][j]) + bb;
            outp[(r + 2) * OUTC + col] = lo32(acc[1][j]) + bb;
            outp[(r + 3) * OUTC + col] = hi32(acc[1][j]) + bb;
        }
    }
    pdl_trigger();
}

// ---------------------------------------------------------------------------
// K3: rollout v5. Block = 8 batches (56 rows), 512 blocks. state prefetched
// before pdl_wait.
// ---------------------------------------------------------------------------
#define RB_BATCH 8
#define RB_ROWS  56
#define RB_OUTF  (RB_BATCH * OUTC)            // 1736
#define RB_YF    (RB_BATCH * NS * NDOF)       // 2856
#define RB_SU    4224
#define RB_SG    (4224 + 1848)                // 6072
#define RB_RG    (6072 + 56)                  // 6128
#define RB_SMEM  ((RB_RG + RB_YF) * 4)        // 35936 bytes

__global__ __launch_bounds__(256) void rollout_kernel(const float* __restrict__ state,
                                                      float* __restrict__ out) {
    extern __shared__ __align__(16) float sm[];
    float2* scfd = reinterpret_cast<float2*>(sm);   // [33][64] slots
    float*  su   = sm + RB_SU;                      // [33][56]
    float*  sg   = sm + RB_SG;                      // [56]
    float*  so   = sm + RB_RG;                      // [1736]
    float*  ybuf = sm + RB_RG;                      // [2856] (after U build)

    const int tid = threadIdx.x;
    const int bbase = blockIdx.x * RB_BATCH;

    // prefetch state (pure harness input) before the PDL wait
    float st0 = state[bbase * NDOF + ((tid < RB_ROWS) ? tid : 0)];

    pdl_wait();   // g_coef_t and g_out217 (K2 outputs) valid

    {
        const float4* src = reinterpret_cast<const float4*>(g_coef_t);
        float4* dst = reinterpret_cast<float4*>(scfd);
        for (int i = tid; i < 1056; i += 256) dst[i] = src[i];
    }
    {
        const float4* p0 = reinterpret_cast<const float4*>(g_out217 + bbase * OUTC);
        const float4* p1 = reinterpret_cast<const float4*>(g_out217 + BO + bbase * OUTC);
        float4* d = reinterpret_cast<float4*>(so);
        for (int i = tid; i < RB_OUTF / 4; i += 256) {
            float4 a = p0[i], b = p1[i];
            d[i] = make_float4(a.x + b.x, a.y + b.y, a.z + b.z, a.w + b.w);
        }
    }
    __syncthreads();

    if (tid < RB_ROWS) {
        int b = tid / NDOF, dof = tid - b * NDOF;
        float goal = so[b * OUTC + dof];
        su[1 * RB_ROWS + tid] = st0;
        su[2 * RB_ROWS + tid] = goal;
        sg[tid] = goal - st0;
    }
    __syncthreads();

    if (tid < 4 * RB_ROWS) {
        const int g = tid / RB_ROWS;
        const int r = tid - g * RB_ROWS;
        const int b = r / NDOF, dof = r - b * NDOF;
        const float sgr = sg[r];
        const float* wsrc = so + b * OUTC + NDOF + dof * NB + g;
        float* udst = su + (3 + g) * RB_ROWS + r;
#pragma unroll
        for (int i = 0; i < 8; i++) {
            int n = g + 4 * i;
            if (n < NB) udst[4 * i * RB_ROWS] = wsrc[4 * i] * sgr;
        }
    }
    __syncthreads();

    if (tid < 224) {
        const int grp = tid / 28;
        const int rp  = tid - grp * 28;
        const float2* cfb = scfd + grp * 8;
        const float*  ub  = su + rp * 2;

        ull acc[7];
        {
            const float4* c4 = reinterpret_cast<const float4*>(cfb);
            float4 c0 = c4[0], c1 = c4[1], c2 = c4[2], c3 = c4[3];
            acc[0] = *reinterpret_cast<const ull*>(&c0.x);
            acc[1] = *reinterpret_cast<const ull*>(&c0.z);
            acc[2] = *reinterpret_cast<const ull*>(&c1.x);
            acc[3] = *reinterpret_cast<const ull*>(&c1.z);
            acc[4] = *reinterpret_cast<const ull*>(&c2.x);
            acc[5] = *reinterpret_cast<const ull*>(&c2.z);
            acc[6] = *reinterpret_cast<const ull*>(&c3.x);
        }
#pragma unroll
        for (int ch = 1; ch < 33; ch++) {
            ull u = *reinterpret_cast<const ull*>(ub + ch * RB_ROWS);
            const float4* c4 = reinterpret_cast<const float4*>(cfb + ch * 64);
            float4 c0 = c4[0], c1 = c4[1], c2 = c4[2], c3 = c4[3];
            fma2(acc[0], u, *reinterpret_cast<const ull*>(&c0.x));
            fma2(acc[1], u, *reinterpret_cast<const ull*>(&c0.z));
            fma2(acc[2], u, *reinterpret_cast<const ull*>(&c1.x));
            fma2(acc[3], u, *reinterpret_cast<const ull*>(&c1.z));
            fma2(acc[4], u, *reinterpret_cast<const ull*>(&c2.x));
            fma2(acc[5], u, *reinterpret_cast<const ull*>(&c2.z));
            fma2(acc[6], u, *reinterpret_cast<const ull*>(&c3.x));
        }
        __syncthreads();   // so -> ybuf reuse

        const int s0 = grp * 7;
        const int cnt = (grp == 7) ? 2 : 7;
#pragma unroll
        for (int p = 0; p < 2; p++) {
            int row = rp * 2 + p;
            int b = row / NDOF, dof = row - b * NDOF;
            float* yb = ybuf + b * (NS * NDOF) + dof + s0 * NDOF;
#pragma unroll
            for (int q = 0; q < 7; q++) {
                if (q < cnt) {
                    float v = p ? hi32(acc[q]) : lo32(acc[q]);
                    yb[q * NDOF] = v;
                }
            }
        }
    } else {
        __syncthreads();
    }
    __syncthreads();

    {
        const float4* s4 = reinterpret_cast<const float4*>(ybuf);
        float4* d4 = reinterpret_cast<float4*>(out + (size_t)blockIdx.x * RB_YF);
        for (int i = tid; i < RB_YF / 4; i += 256) d4[i] = s4[i];
    }
}

// ---------------------------------------------------------------------------
extern "C" void kernel_launch(void* const* d_in, const int* in_sizes, int n_in,
                              void* d_out, int out_size) {
    const float* x      = (const float*)d_in[0];
    const float* state  = (const float*)d_in[1];
    const float* W_pt   = (const float*)d_in[2];
    const float* b_pt   = (const float*)d_in[3];
    const float* W_last = (const float*)d_in[4];
    const float* b_last = (const float*)d_in[5];
    const float* c      = (const float*)d_in[6];
    const float* h      = (const float*)d_in[7];
    float* out = (float*)d_out;

    static int init_done = 0;
    if (!init_done) {
        cudaFuncSetAttribute(k1_kernel, cudaFuncAttributeMaxDynamicSharedMemorySize,
                             K1_SMEM);
        cudaFuncSetAttribute(rollout_kernel, cudaFuncAttributeMaxDynamicSharedMemorySize,
                             RB_SMEM);
        init_done = 1;
    }

    // K1: coef (blocks 0..50) + gemm1 (blocks 51..306)
    k1_kernel<<<307, 256, K1_SMEM>>>(x, W_pt, b_pt, c, h);

    // K2: gemm2, PDL-chained to K1
    {
        cudaLaunchConfig_t cfg = {};
        cfg.gridDim = dim3(BATCH / 64, 2, 2);
        cfg.blockDim = dim3(256, 1, 1);
        cfg.dynamicSmemBytes = 0;
        cfg.stream = 0;
        cudaLaunchAttribute attr[1];
        attr[0].id = cudaLaunchAttributeProgrammaticStreamSerialization;
        attr[0].val.programmaticStreamSerializationAllowed = 1;
        cfg.attrs = attr;
        cfg.numAttrs = 1;
        cudaLaunchKernelEx(&cfg, gemm2_kernel, W_last, b_last);
    }

    // K3: rollout, PDL-chained to K2
    {
        cudaLaunchConfig_t cfg = {};
        cfg.gridDim = dim3(BATCH / RB_BATCH, 1, 1);
        cfg.blockDim = dim3(256, 1, 1);
        cfg.dynamicSmemBytes = RB_SMEM;
        cfg.stream = 0;
        cudaLaunchAttribute attr[1];
        attr[0].id = cudaLaunchAttributeProgrammaticStreamSerialization;
        attr[0].val.programmaticStreamSerializationAllowed = 1;
        cfg.attrs = attr;
        cfg.numAttrs = 1;
        cudaLaunchKernelEx(&cfg, rollout_kernel, (const float*)state, (float*)out);
    }
}